// round 2
// baseline (speedup 1.0000x reference)
#include <cuda_runtime.h>

#define BB 64
#define SS 512
#define HH 768
#define CC 9
#define L2E 1.4426950408889634f
#define LN2 0.6931471805599453f
#define FULLMASK 0xffffffffu

// scratch (no allocations allowed) — 16B-aligned for vector access
__device__ __align__(16) float g_emis[BB * SS * CC];   // 1.18 MB
__device__ float g_llh[BB];

__device__ __forceinline__ float ex2f(float x) {
    float y; asm("ex2.approx.ftz.f32 %0, %1;" : "=f"(y) : "f"(x)); return y;
}
__device__ __forceinline__ float lg2f(float x) {
    float y; asm("lg2.approx.ftz.f32 %0, %1;" : "=f"(y) : "f"(x)); return y;
}

// ---------------------------------------------------------------------------
// Kernel 1: emissions = hidden @ W^T + b
// warp computes 4 rows at a time (amortize smem W reads), grid-stride.
// ---------------------------------------------------------------------------
__global__ __launch_bounds__(256) void emis_kernel(
    const float* __restrict__ hidden,
    const float* __restrict__ W,
    const float* __restrict__ bias)
{
    __shared__ alignas(16) float Wsm[CC * HH];   // 27648 B
    // cooperative load of W (float4)
    for (int i = threadIdx.x; i < CC * HH / 4; i += 256)
        ((float4*)Wsm)[i] = ((const float4*)W)[i];
    __syncthreads();

    float bv[CC];
#pragma unroll
    for (int c = 0; c < CC; c++) bv[c] = bias[c];

    const int lane   = threadIdx.x & 31;
    const int warp   = (blockIdx.x * blockDim.x + threadIdx.x) >> 5;
    const int nwarps = gridDim.x * (blockDim.x >> 5);
    const int NGROUPS = (BB * SS) / 4;   // 8192 groups of 4 rows

    for (int g = warp; g < NGROUPS; g += nwarps) {
        const int row0 = g * 4;
        float acc[4][CC];
#pragma unroll
        for (int r = 0; r < 4; r++)
#pragma unroll
            for (int c = 0; c < CC; c++) acc[r][c] = 0.0f;

#pragma unroll
        for (int i = 0; i < HH / 128; i++) {   // 6 iterations
            float4 h[4];
#pragma unroll
            for (int r = 0; r < 4; r++)
                h[r] = ((const float4*)(hidden + (size_t)(row0 + r) * HH))[i * 32 + lane];
#pragma unroll
            for (int c = 0; c < CC; c++) {
                float4 w = ((const float4*)(Wsm + c * HH))[i * 32 + lane];
#pragma unroll
                for (int r = 0; r < 4; r++) {
                    acc[r][c] = fmaf(h[r].x, w.x, acc[r][c]);
                    acc[r][c] = fmaf(h[r].y, w.y, acc[r][c]);
                    acc[r][c] = fmaf(h[r].z, w.z, acc[r][c]);
                    acc[r][c] = fmaf(h[r].w, w.w, acc[r][c]);
                }
            }
        }
        // butterfly reduce each of the 36 partials across the warp
#pragma unroll
        for (int r = 0; r < 4; r++)
#pragma unroll
            for (int c = 0; c < CC; c++)
#pragma unroll
                for (int off = 16; off > 0; off >>= 1)
                    acc[r][c] += __shfl_xor_sync(FULLMASK, acc[r][c], off);

        if (lane == 0) {
#pragma unroll
            for (int r = 0; r < 4; r++)
#pragma unroll
                for (int c = 0; c < CC; c++)
                    g_emis[(size_t)(row0 + r) * CC + c] = acc[r][c] + bv[c];
        }
    }
}

// ---------------------------------------------------------------------------
// Kernel 2: per-batch CRF forward scan + numerator. One warp per batch.
// ---------------------------------------------------------------------------
__global__ __launch_bounds__(32) void crf_kernel(
    const float* __restrict__ stv,
    const float* __restrict__ trv,
    const float* __restrict__ etv,
    const int*   __restrict__ tags,
    const int*   __restrict__ mask)
{
    __shared__ alignas(16) float emit_sm[SS * CC];   // 18432 B
    __shared__ alignas(16) int   tags_sm[SS];
    __shared__ float tr_sm[CC * CC];
    __shared__ float st_sm[CC], et_sm[CC];

    const int b    = blockIdx.x;
    const int lane = threadIdx.x;

    // load emissions row (float4)
    {
        const float4* src = (const float4*)(g_emis + (size_t)b * SS * CC);
        float4* dst = (float4*)emit_sm;
        for (int i = lane; i < SS * CC / 4; i += 32) dst[i] = src[i];
    }
    for (int i = lane; i < CC * CC; i += 32) tr_sm[i] = trv[i];
    if (lane < CC) { st_sm[lane] = stv[lane]; et_sm[lane] = etv[lane]; }
    {
        const int4* src = (const int4*)(tags + (size_t)b * SS);
        int4* dst = (int4*)tags_sm;
        for (int i = lane; i < SS / 4; i += 32) dst[i] = src[i];
    }
    // sequence length (mask is a prefix of ones)
    int mcount = 0;
    {
        const int* mrow = mask + (size_t)b * SS;
        for (int t = lane; t < SS; t += 32) mcount += mrow[t];
#pragma unroll
        for (int off = 16; off > 0; off >>= 1)
            mcount += __shfl_xor_sync(FULLMASK, mcount, off);
    }
    const int len = mcount;   // >= S/2 >= 1
    __syncthreads();

    // ---- numerator (gold path score) ----
    float np = 0.0f;
    for (int t = 1 + lane; t < len; t += 32) {
        int tp = tags_sm[t - 1];
        int tc = tags_sm[t];
        np += tr_sm[tp * CC + tc] + emit_sm[t * CC + tc];
    }
#pragma unroll
    for (int off = 16; off > 0; off >>= 1)
        np += __shfl_xor_sync(FULLMASK, np, off);
    const int t0 = tags_sm[0];
    const int tl = tags_sm[len - 1];
    const float num = np + st_sm[t0] + emit_sm[t0] + et_sm[tl];

    // ---- forward scan (log-space). lane c owns alpha[c]. ----
    const int c = (lane < CC) ? lane : 0;
    float trl[CC];   // tr[j][c] * log2(e)
#pragma unroll
    for (int j = 0; j < CC; j++) trl[j] = tr_sm[j * CC + c] * L2E;

    float score = st_sm[c] + emit_sm[c];   // t = 0

    for (int t = 1; t < len; t++) {
        const float er = emit_sm[t * CC + c];
        const float K  = score;           // own previous value: bounded offset
        const float kb = K * L2E;
        const float base = K + er;
        float q[CC];
#pragma unroll
        for (int j = 0; j < CC; j++) q[j] = trl[j] - kb;
        float s[CC];
#pragma unroll
        for (int j = 0; j < CC; j++) s[j] = __shfl_sync(FULLMASK, score, j);
        float e[CC];
#pragma unroll
        for (int j = 0; j < CC; j++) e[j] = ex2f(fmaf(s[j], L2E, q[j]));
        // balanced add tree (depth 4)
        float e01 = e[0] + e[1], e23 = e[2] + e[3];
        float e45 = e[4] + e[5], e67 = e[6] + e[7];
        float sum = ((e01 + e23) + (e45 + e67)) + e[8];
        score = fmaf(lg2f(sum), LN2, base);
    }

    // ---- denominator: logsumexp(score + et) over classes ----
    float v = (lane < CC) ? (score + et_sm[lane]) : -3.0e38f;
    float m = v;
#pragma unroll
    for (int off = 16; off > 0; off >>= 1)
        m = fmaxf(m, __shfl_xor_sync(FULLMASK, m, off));
    float se = (lane < CC) ? ex2f((v - m) * L2E) : 0.0f;
#pragma unroll
    for (int off = 16; off > 0; off >>= 1)
        se += __shfl_xor_sync(FULLMASK, se, off);
    const float denom = fmaf(lg2f(se), LN2, m);

    if (lane == 0) g_llh[b] = num - denom;
}

// ---------------------------------------------------------------------------
// Kernel 3: out = -mean(llh)
// ---------------------------------------------------------------------------
__global__ __launch_bounds__(32) void final_kernel(float* __restrict__ out)
{
    const int lane = threadIdx.x;
    float s = g_llh[lane] + g_llh[lane + 32];
#pragma unroll
    for (int off = 16; off > 0; off >>= 1)
        s += __shfl_xor_sync(FULLMASK, s, off);
    if (lane == 0) out[0] = -s * (1.0f / (float)BB);
}

// ---------------------------------------------------------------------------
extern "C" void kernel_launch(void* const* d_in, const int* in_sizes, int n_in,
                              void* d_out, int out_size)
{
    (void)in_sizes; (void)n_in; (void)out_size;
    const float* hidden = (const float*)d_in[0];
    const float* W      = (const float*)d_in[1];
    const float* bias   = (const float*)d_in[2];
    const float* stv    = (const float*)d_in[3];
    const float* trv    = (const float*)d_in[4];
    const float* etv    = (const float*)d_in[5];
    const int*   tags   = (const int*)d_in[6];
    const int*   mask   = (const int*)d_in[7];

    emis_kernel<<<592, 256>>>(hidden, W, bias);
    crf_kernel<<<BB, 32>>>(stv, trv, etv, tags, mask);
    final_kernel<<<1, 32>>>((float*)d_out);
}

// round 3
// speedup vs baseline: 1.5016x; 1.5016x over previous
#include <cuda_runtime.h>

#define BB 64
#define SS 512
#define HH 768
#define CC 9
#define L2E 1.4426950408889634f
#define LN2 0.6931471805599453f
#define FULLMASK 0xffffffffu

// scratch (no allocations allowed) — 16B-aligned for vector access
__device__ __align__(16) float g_emis[BB * SS * CC];   // 1.18 MB
__device__ float g_llh[BB];

__device__ __forceinline__ float ex2f(float x) {
    float y; asm("ex2.approx.ftz.f32 %0, %1;" : "=f"(y) : "f"(x)); return y;
}
__device__ __forceinline__ float lg2f(float x) {
    float y; asm("lg2.approx.ftz.f32 %0, %1;" : "=f"(y) : "f"(x)); return y;
}

// ---------------------------------------------------------------------------
// Kernel 1: emissions = hidden @ W^T + b
// warp computes 2 rows; moderate unroll; 24 warps/SM for latency hiding.
// ---------------------------------------------------------------------------
__global__ __launch_bounds__(256, 3) void emis_kernel(
    const float* __restrict__ hidden,
    const float* __restrict__ W,
    const float* __restrict__ bias)
{
    __shared__ alignas(16) float Wsm[CC * HH];   // 27648 B
    for (int i = threadIdx.x; i < CC * HH / 4; i += 256)
        ((float4*)Wsm)[i] = ((const float4*)W)[i];
    __syncthreads();

    float bv[CC];
#pragma unroll
    for (int c = 0; c < CC; c++) bv[c] = bias[c];

    const int lane   = threadIdx.x & 31;
    const int warp   = (blockIdx.x * blockDim.x + threadIdx.x) >> 5;
    const int nwarps = gridDim.x * (blockDim.x >> 5);
    const int NGROUPS = (BB * SS) / 2;   // 16384 groups of 2 rows

    for (int g = warp; g < NGROUPS; g += nwarps) {
        const int row0 = g * 2;
        const float4* h0p = (const float4*)(hidden + (size_t)row0 * HH);
        const float4* h1p = (const float4*)(hidden + (size_t)(row0 + 1) * HH);

        float acc[2][CC];
#pragma unroll
        for (int r = 0; r < 2; r++)
#pragma unroll
            for (int c = 0; c < CC; c++) acc[r][c] = 0.0f;

#pragma unroll 2
        for (int i = 0; i < HH / 128; i++) {   // 6 iterations
            float4 h0 = h0p[i * 32 + lane];
            float4 h1 = h1p[i * 32 + lane];
#pragma unroll
            for (int c = 0; c < CC; c++) {
                float4 w = ((const float4*)(Wsm + c * HH))[i * 32 + lane];
                acc[0][c] = fmaf(h0.x, w.x, acc[0][c]);
                acc[0][c] = fmaf(h0.y, w.y, acc[0][c]);
                acc[0][c] = fmaf(h0.z, w.z, acc[0][c]);
                acc[0][c] = fmaf(h0.w, w.w, acc[0][c]);
                acc[1][c] = fmaf(h1.x, w.x, acc[1][c]);
                acc[1][c] = fmaf(h1.y, w.y, acc[1][c]);
                acc[1][c] = fmaf(h1.z, w.z, acc[1][c]);
                acc[1][c] = fmaf(h1.w, w.w, acc[1][c]);
            }
        }
        // butterfly reduce each of the 18 partials across the warp
#pragma unroll
        for (int r = 0; r < 2; r++)
#pragma unroll
            for (int c = 0; c < CC; c++)
#pragma unroll
                for (int off = 16; off > 0; off >>= 1)
                    acc[r][c] += __shfl_xor_sync(FULLMASK, acc[r][c], off);

        if (lane == 0) {
#pragma unroll
            for (int r = 0; r < 2; r++)
#pragma unroll
                for (int c = 0; c < CC; c++)
                    g_emis[(size_t)(row0 + r) * CC + c] = acc[r][c] + bv[c];
        }
    }
}

// ---------------------------------------------------------------------------
// Kernel 2: per-batch CRF forward scan (linear domain) + numerator.
// One warp per batch. Lane c owns alpha[c] (linear, rescaled by 2^-esum).
// ---------------------------------------------------------------------------
__global__ __launch_bounds__(32) void crf_kernel(
    const float* __restrict__ stv,
    const float* __restrict__ trv,
    const float* __restrict__ etv,
    const int*   __restrict__ tags,
    const int*   __restrict__ mask)
{
    __shared__ alignas(16) float emit_sm[SS * CC];   // 18432 B
    __shared__ alignas(16) int   tags_sm[SS];
    __shared__ float tr_sm[CC * CC];
    __shared__ float st_sm[CC], et_sm[CC];

    const int b    = blockIdx.x;
    const int lane = threadIdx.x;

    {
        const float4* src = (const float4*)(g_emis + (size_t)b * SS * CC);
        float4* dst = (float4*)emit_sm;
        for (int i = lane; i < SS * CC / 4; i += 32) dst[i] = src[i];
    }
    for (int i = lane; i < CC * CC; i += 32) tr_sm[i] = trv[i];
    if (lane < CC) { st_sm[lane] = stv[lane]; et_sm[lane] = etv[lane]; }
    {
        const int4* src = (const int4*)(tags + (size_t)b * SS);
        int4* dst = (int4*)tags_sm;
        for (int i = lane; i < SS / 4; i += 32) dst[i] = src[i];
    }
    // sequence length (mask is a prefix of ones)
    int mcount = 0;
    {
        const int* mrow = mask + (size_t)b * SS;
        for (int t = lane; t < SS; t += 32) mcount += mrow[t];
#pragma unroll
        for (int off = 16; off > 0; off >>= 1)
            mcount += __shfl_xor_sync(FULLMASK, mcount, off);
    }
    const int len = mcount;
    __syncthreads();

    // ---- numerator (gold path score) ----
    float np = 0.0f;
    for (int t = 1 + lane; t < len; t += 32) {
        int tp = tags_sm[t - 1];
        int tc = tags_sm[t];
        np += tr_sm[tp * CC + tc] + emit_sm[t * CC + tc];
    }
#pragma unroll
    for (int off = 16; off > 0; off >>= 1)
        np += __shfl_xor_sync(FULLMASK, np, off);
    const int t0 = tags_sm[0];
    const int tl = tags_sm[len - 1];
    const float num = np + st_sm[t0] + emit_sm[t0] + et_sm[tl];

    // ---- forward scan, linear domain ----
    const int c = (lane < CC) ? lane : 0;
    float Te[CC];                    // exp(tr[j][c])
#pragma unroll
    for (int j = 0; j < CC; j++) Te[j] = ex2f(tr_sm[j * CC + c] * L2E);

    float a    = ex2f((st_sm[c] + emit_sm[c]) * L2E);   // alpha at t=0 (linear)
    int   esum = 0;                                      // accumulated 2^esum scale
    // pipeline: exp(emission) for step t computed during step t-1
    float em_lin = ex2f(emit_sm[CC + c] * L2E);          // for t=1 (safe: len>=1; row exists)

    for (int t = 1; t < len; t++) {
        // prefetch next step's raw emission and start its ex2 early
        const float em_next_raw = (t + 1 < SS) ? emit_sm[(t + 1) * CC + c] : 0.0f;

        float s0 = __shfl_sync(FULLMASK, a, 0);
        float s1 = __shfl_sync(FULLMASK, a, 1);
        float s2 = __shfl_sync(FULLMASK, a, 2);
        float s3 = __shfl_sync(FULLMASK, a, 3);
        float s4 = __shfl_sync(FULLMASK, a, 4);
        float s5 = __shfl_sync(FULLMASK, a, 5);
        float s6 = __shfl_sync(FULLMASK, a, 6);
        float s7 = __shfl_sync(FULLMASK, a, 7);
        float s8 = __shfl_sync(FULLMASK, a, 8);

        // uniform power-of-two rescale from lane 0's exponent (pure ALU, off
        // the critical tree path; s0 > 0 always)
        const int eb  = ((int)(__float_as_int(s0) >> 23)) & 0xff;  // biased exp
        const float pot = __int_as_float((254 - eb) << 23);        // 2^{-(eb-127)}
        const float emp = em_lin * pot;
        esum += eb - 127;

        float p0 = s0 * Te[0], p1 = s1 * Te[1], p2 = s2 * Te[2];
        float p3 = s3 * Te[3], p4 = s4 * Te[4], p5 = s5 * Te[5];
        float p6 = s6 * Te[6], p7 = s7 * Te[7], p8 = s8 * Te[8];
        float q0 = p0 + p1, q1 = p2 + p3, q2 = p4 + p5, q3 = p6 + p7;
        float sum = ((q0 + q1) + (q2 + q3)) + p8;

        a = sum * emp;
        em_lin = ex2f(em_next_raw * L2E);
    }

    // ---- denominator: log(sum_c a_c * exp(et_c)) + esum*ln2 ----
    float v = (lane < CC) ? a * ex2f(et_sm[lane] * L2E) : 0.0f;
#pragma unroll
    for (int off = 16; off > 0; off >>= 1)
        v += __shfl_xor_sync(FULLMASK, v, off);
    const float denom = (lg2f(v) + (float)esum) * LN2;

    if (lane == 0) g_llh[b] = num - denom;
}

// ---------------------------------------------------------------------------
// Kernel 3: out = -mean(llh)
// ---------------------------------------------------------------------------
__global__ __launch_bounds__(32) void final_kernel(float* __restrict__ out)
{
    const int lane = threadIdx.x;
    float s = g_llh[lane] + g_llh[lane + 32];
#pragma unroll
    for (int off = 16; off > 0; off >>= 1)
        s += __shfl_xor_sync(FULLMASK, s, off);
    if (lane == 0) out[0] = -s * (1.0f / (float)BB);
}

// ---------------------------------------------------------------------------
extern "C" void kernel_launch(void* const* d_in, const int* in_sizes, int n_in,
                              void* d_out, int out_size)
{
    (void)in_sizes; (void)n_in; (void)out_size;
    const float* hidden = (const float*)d_in[0];
    const float* W      = (const float*)d_in[1];
    const float* bias   = (const float*)d_in[2];
    const float* stv    = (const float*)d_in[3];
    const float* trv    = (const float*)d_in[4];
    const float* etv    = (const float*)d_in[5];
    const int*   tags   = (const int*)d_in[6];
    const int*   mask   = (const int*)d_in[7];

    emis_kernel<<<444, 256>>>(hidden, W, bias);
    crf_kernel<<<BB, 32>>>(stv, trv, etv, tags, mask);
    final_kernel<<<1, 32>>>((float*)d_out);
}

// round 4
// speedup vs baseline: 1.8064x; 1.2030x over previous
#include <cuda_runtime.h>

#define BB 64
#define SS 512
#define HH 768
#define CC 9
#define L2E 1.4426950408889634f
#define LN2 0.6931471805599453f
#define FULLMASK 0xffffffffu

#define KCH 24      // chunks per batch
#define CH  22      // steps per chunk (24*22 >= 511)
#define WPB 8       // warps per batch in chunk kernel (3 chunks per warp)

// scratch (no allocations allowed)
__device__ __align__(16) float g_emis[BB * SS * CC];    // 1.18 MB
__device__ __align__(16) float g_P[BB * KCH * 81];      // chunk matrices
__device__ int   g_esum[BB * KCH * CC];                 // per-row exponents
__device__ float g_num[BB * WPB];                       // numerator partials
__device__ float g_llh[BB];

__device__ __forceinline__ float ex2f(float x) {
    float y; asm("ex2.approx.ftz.f32 %0, %1;" : "=f"(y) : "f"(x)); return y;
}
__device__ __forceinline__ float lg2f(float x) {
    float y; asm("lg2.approx.ftz.f32 %0, %1;" : "=f"(y) : "f"(x)); return y;
}

// ---------------------------------------------------------------------------
// Kernel 1: emissions = hidden @ W^T + b.  4 rows per warp (amortize W LDS).
// ---------------------------------------------------------------------------
__global__ __launch_bounds__(256, 2) void emis_kernel(
    const float* __restrict__ hidden,
    const float* __restrict__ W,
    const float* __restrict__ bias)
{
    __shared__ alignas(16) float Wsm[CC * HH];   // 27648 B
    for (int i = threadIdx.x; i < CC * HH / 4; i += 256)
        ((float4*)Wsm)[i] = ((const float4*)W)[i];
    __syncthreads();

    float bv[CC];
#pragma unroll
    for (int c = 0; c < CC; c++) bv[c] = bias[c];

    const int lane   = threadIdx.x & 31;
    const int warp   = (blockIdx.x * blockDim.x + threadIdx.x) >> 5;
    const int nwarps = gridDim.x * (blockDim.x >> 5);
    const int NGROUPS = (BB * SS) / 4;   // 8192 groups of 4 rows

    for (int g = warp; g < NGROUPS; g += nwarps) {
        const int row0 = g * 4;
        const float4* hp[4];
#pragma unroll
        for (int r = 0; r < 4; r++)
            hp[r] = (const float4*)(hidden + (size_t)(row0 + r) * HH);

        float acc[4][CC];
#pragma unroll
        for (int r = 0; r < 4; r++)
#pragma unroll
            for (int c = 0; c < CC; c++) acc[r][c] = 0.0f;

#pragma unroll 1
        for (int i = 0; i < HH / 128; i++) {   // 6 iterations
            float4 h[4];
#pragma unroll
            for (int r = 0; r < 4; r++) h[r] = hp[r][i * 32 + lane];
#pragma unroll
            for (int c = 0; c < CC; c++) {
                float4 w = ((const float4*)(Wsm + c * HH))[i * 32 + lane];
#pragma unroll
                for (int r = 0; r < 4; r++) {
                    acc[r][c] = fmaf(h[r].x, w.x, acc[r][c]);
                    acc[r][c] = fmaf(h[r].y, w.y, acc[r][c]);
                    acc[r][c] = fmaf(h[r].z, w.z, acc[r][c]);
                    acc[r][c] = fmaf(h[r].w, w.w, acc[r][c]);
                }
            }
        }
#pragma unroll
        for (int r = 0; r < 4; r++)
#pragma unroll
            for (int c = 0; c < CC; c++)
#pragma unroll
                for (int off = 16; off > 0; off >>= 1)
                    acc[r][c] += __shfl_xor_sync(FULLMASK, acc[r][c], off);

        if (lane == 0) {
#pragma unroll
            for (int r = 0; r < 4; r++)
#pragma unroll
                for (int c = 0; c < CC; c++)
                    g_emis[(size_t)(row0 + r) * CC + c] = acc[r][c] + bv[c];
        }
    }
}

// ---------------------------------------------------------------------------
// Kernel 2: chunk matrix products (linear domain) + numerator partials.
// grid (WPB, BB), one warp per block. Lane = (s, r): sub-chunk s in {0,1,2},
// matrix row r in [0,9). Lane r holds row r of M; M <- M * A_t per step.
// Per-row power-of-two rescale (lane-local, exact, tracked in esum).
// ---------------------------------------------------------------------------
__global__ __launch_bounds__(32) void crf_chunk_kernel(
    const float* __restrict__ trv,
    const int*   __restrict__ tags,
    const int*   __restrict__ mask)
{
    __shared__ float em_s[3 * CH * CC];   // 594 floats

    const int b    = blockIdx.y;
    const int w    = blockIdx.x;
    const int lane = threadIdx.x;
    const int s = (lane < 27) ? (lane / 9) : 2;
    const int r = (lane < 27) ? (lane % 9) : 8;

    // Te[j][c] = exp(tr[j][c])  (81 registers, same in every lane)
    float Te[81];
#pragma unroll
    for (int jc = 0; jc < 81; jc++) Te[jc] = ex2f(trv[jc] * L2E);

    // stage this warp's 66 steps of emissions (contiguous in g_emis)
    const int tb = 1 + 3 * CH * w;           // first t of this warp's window
    {
        const float* src = g_emis + ((size_t)b * SS + tb) * CC;
        for (int idx = lane; idx < 3 * CH * CC; idx += 32) {
            int tt = tb + idx / CC;
            em_s[idx] = (tt < SS) ? src[idx] : 0.0f;
        }
    }
    // sequence length
    int mcount = 0;
    {
        const int* mrow = mask + (size_t)b * SS;
        for (int t = lane; t < SS; t += 32) mcount += mrow[t];
#pragma unroll
        for (int off = 16; off > 0; off >>= 1)
            mcount += __shfl_xor_sync(FULLMASK, mcount, off);
    }
    const int len = mcount;
    __syncwarp();

    // ---- matrix product over this sub-chunk ----
    float m[9];
#pragma unroll
    for (int c = 0; c < CC; c++) m[c] = (c == r) ? 1.0f : 0.0f;
    int esum = 0;
    const int k  = 3 * w + s;
    const int t0 = 1 + CH * k;

#pragma unroll 1
    for (int i = 0; i < CH; i++) {
        const int t = t0 + i;
        const bool act = (t < len);          // len <= SS covers t>=SS too
        float eml[9];
#pragma unroll
        for (int c = 0; c < CC; c++)
            eml[c] = ex2f(em_s[(s * CH + i) * CC + c] * L2E);
        float v[9];
#pragma unroll
        for (int c = 0; c < CC; c++) {
            float d = m[0] * Te[0 * 9 + c];
#pragma unroll
            for (int j = 1; j < CC; j++) d = fmaf(m[j], Te[j * 9 + c], d);
            v[c] = d * eml[c];
        }
        // row max -> power-of-two rescale (exact)
        float mx01 = fmaxf(v[0], v[1]), mx23 = fmaxf(v[2], v[3]);
        float mx45 = fmaxf(v[4], v[5]), mx67 = fmaxf(v[6], v[7]);
        float mx = fmaxf(fmaxf(fmaxf(mx01, mx23), fmaxf(mx45, mx67)), v[8]);
        int eb = (__float_as_int(mx) >> 23) & 0xff;
        float pot = __int_as_float((254 - eb) << 23);
#pragma unroll
        for (int c = 0; c < CC; c++) m[c] = act ? v[c] * pot : m[c];
        esum += act ? (eb - 127) : 0;
    }
    if (lane < 27) {
        float* dst = g_P + ((size_t)b * KCH + k) * 81 + r * 9;
#pragma unroll
        for (int c = 0; c < CC; c++) dst[c] = m[c];
        g_esum[((size_t)b * KCH + k) * CC + r] = esum;
    }

    // ---- numerator partial over t in [tb, tb + 66) ----
    float np = 0.0f;
    const int* trow = tags + (size_t)b * SS;
    for (int i = lane; i < 3 * CH; i += 32) {
        int t = tb + i;
        if (t < len) {
            int tp = trow[t - 1];
            int tc = trow[t];
            np += trv[tp * CC + tc] + g_emis[((size_t)b * SS + t) * CC + tc];
        }
    }
#pragma unroll
    for (int off = 16; off > 0; off >>= 1)
        np += __shfl_xor_sync(FULLMASK, np, off);
    if (lane == 0) g_num[b * WPB + w] = np;
}

// ---------------------------------------------------------------------------
// Kernel 3: combine chunk matrices per batch (24 prefetched matvecs),
// numerator assembly, denominator, llh.
// ---------------------------------------------------------------------------
__global__ __launch_bounds__(32) void crf_combine_kernel(
    const float* __restrict__ stv,
    const float* __restrict__ etv,
    const int*   __restrict__ tags,
    const int*   __restrict__ mask)
{
    const int b    = blockIdx.x;
    const int lane = threadIdx.x;
    const int c    = (lane < CC) ? lane : 0;
    const bool on  = (lane < CC);

    // sequence length
    int mcount = 0;
    {
        const int* mrow = mask + (size_t)b * SS;
        for (int t = lane; t < SS; t += 32) mcount += mrow[t];
#pragma unroll
        for (int off = 16; off > 0; off >>= 1)
            mcount += __shfl_xor_sync(FULLMASK, mcount, off);
    }
    const int len = mcount;

    // alpha at t=0 (linear)
    float a = on ? ex2f((stv[c] + g_emis[(size_t)b * SS * CC + c]) * L2E) : 0.0f;
    int E = 0;

    // prefetch chunk 0
    const float* Pb = g_P + (size_t)b * KCH * 81;
    const int*   Eb = g_esum + (size_t)b * KCH * CC;
    int ejn = on ? Eb[lane] : (-1 << 30);
    float Pn[9];
#pragma unroll
    for (int j = 0; j < CC; j++) Pn[j] = Pb[j * 9 + c];

#pragma unroll 1
    for (int k = 0; k < KCH; k++) {
        int ej = ejn;
        float P[9];
#pragma unroll
        for (int j = 0; j < CC; j++) P[j] = Pn[j];
        if (k + 1 < KCH) {
            ejn = on ? Eb[(k + 1) * CC + lane] : (-1 << 30);
#pragma unroll
            for (int j = 0; j < CC; j++) Pn[j] = Pb[(k + 1) * 81 + j * 9 + c];
        }
        // row-exponent alignment: scale a_j by 2^(e_j - emax)
        int emax = ej;
#pragma unroll
        for (int off = 16; off > 0; off >>= 1)
            emax = max(emax, __shfl_xor_sync(FULLMASK, emax, off));
        int d = ej - emax;
        float sc = (d > -126) ? __int_as_float((d + 127) << 23) : 0.0f;
        float ap = a * sc;
        E += emax;

        float s0 = __shfl_sync(FULLMASK, ap, 0);
        float s1 = __shfl_sync(FULLMASK, ap, 1);
        float s2 = __shfl_sync(FULLMASK, ap, 2);
        float s3 = __shfl_sync(FULLMASK, ap, 3);
        float s4 = __shfl_sync(FULLMASK, ap, 4);
        float s5 = __shfl_sync(FULLMASK, ap, 5);
        float s6 = __shfl_sync(FULLMASK, ap, 6);
        float s7 = __shfl_sync(FULLMASK, ap, 7);
        float s8 = __shfl_sync(FULLMASK, ap, 8);

        float na = s0 * P[0];
        na = fmaf(s1, P[1], na); na = fmaf(s2, P[2], na);
        na = fmaf(s3, P[3], na); na = fmaf(s4, P[4], na);
        na = fmaf(s5, P[5], na); na = fmaf(s6, P[6], na);
        na = fmaf(s7, P[7], na); na = fmaf(s8, P[8], na);
        na = on ? na : 0.0f;

        // renormalize alpha
        float mxa = na;
#pragma unroll
        for (int off = 16; off > 0; off >>= 1)
            mxa = fmaxf(mxa, __shfl_xor_sync(FULLMASK, mxa, off));
        int eb = (__float_as_int(mxa) >> 23) & 0xff;
        float pot = __int_as_float((254 - eb) << 23);
        a = na * pot;
        E += eb - 127;
    }

    // denominator
    float term = on ? a * ex2f(etv[c] * L2E) : 0.0f;
#pragma unroll
    for (int off = 16; off > 0; off >>= 1)
        term += __shfl_xor_sync(FULLMASK, term, off);
    const float denom = (lg2f(term) + (float)E) * LN2;

    // numerator
    float np = (lane < WPB) ? g_num[b * WPB + lane] : 0.0f;
#pragma unroll
    for (int off = 16; off > 0; off >>= 1)
        np += __shfl_xor_sync(FULLMASK, np, off);
    const int first = tags[(size_t)b * SS];
    const int last  = tags[(size_t)b * SS + len - 1];
    const float num = np + stv[first] + g_emis[((size_t)b * SS) * CC + first] + etv[last];

    if (lane == 0) g_llh[b] = num - denom;
}

// ---------------------------------------------------------------------------
// Kernel 4: out = -mean(llh)
// ---------------------------------------------------------------------------
__global__ __launch_bounds__(32) void final_kernel(float* __restrict__ out)
{
    const int lane = threadIdx.x;
    float s = g_llh[lane] + g_llh[lane + 32];
#pragma unroll
    for (int off = 16; off > 0; off >>= 1)
        s += __shfl_xor_sync(FULLMASK, s, off);
    if (lane == 0) out[0] = -s * (1.0f / (float)BB);
}

// ---------------------------------------------------------------------------
extern "C" void kernel_launch(void* const* d_in, const int* in_sizes, int n_in,
                              void* d_out, int out_size)
{
    (void)in_sizes; (void)n_in; (void)out_size;
    const float* hidden = (const float*)d_in[0];
    const float* W      = (const float*)d_in[1];
    const float* bias   = (const float*)d_in[2];
    const float* stv    = (const float*)d_in[3];
    const float* trv    = (const float*)d_in[4];
    const float* etv    = (const float*)d_in[5];
    const int*   tags   = (const int*)d_in[6];
    const int*   mask   = (const int*)d_in[7];

    emis_kernel<<<296, 256>>>(hidden, W, bias);
    dim3 cgrid(WPB, BB);
    crf_chunk_kernel<<<cgrid, 32>>>(trv, tags, mask);
    crf_combine_kernel<<<BB, 32>>>(stv, etv, tags, mask);
    final_kernel<<<1, 32>>>((float*)d_out);
}